// round 1
// baseline (speedup 1.0000x reference)
#include <cuda_runtime.h>
#include <math.h>

#define DIMD   1024
#define HEADS  16
#define DH     64
#define INNER  1024
#define BATCH  4
#define SEQ    2048
#define ROWS   (BATCH*SEQ)      // 8192
#define QKVW   (3*INNER)        // 3072

// Scratch (device globals: allocation-free contract)
__device__ float g_xn [ROWS*DIMD];        // 32 MB
__device__ float g_qkv[ROWS*QKVW];        // 96 MB
__device__ float g_att[ROWS*INNER];       // 32 MB

// ---------------------------------------------------------------------------
// LayerNorm: one block per row, 256 threads, float4 (1024 = 256*4)
// ---------------------------------------------------------------------------
__global__ void ln_kernel(const float* __restrict__ x,
                          const float* __restrict__ gamma,
                          const float* __restrict__ beta,
                          float* __restrict__ out) {
    int row = blockIdx.x;
    int tid = threadIdx.x;
    const float4* xr = reinterpret_cast<const float4*>(x + (size_t)row * DIMD);
    float4 v = xr[tid];
    float s  = v.x + v.y + v.z + v.w;
    float ss = v.x*v.x + v.y*v.y + v.z*v.z + v.w*v.w;
    #pragma unroll
    for (int o = 16; o > 0; o >>= 1) {
        s  += __shfl_xor_sync(0xFFFFFFFFu, s,  o);
        ss += __shfl_xor_sync(0xFFFFFFFFu, ss, o);
    }
    __shared__ float rs[8], rq[8];
    int w = tid >> 5, l = tid & 31;
    if (l == 0) { rs[w] = s; rq[w] = ss; }
    __syncthreads();
    if (w == 0) {
        s  = (l < 8) ? rs[l] : 0.f;
        ss = (l < 8) ? rq[l] : 0.f;
        #pragma unroll
        for (int o = 4; o > 0; o >>= 1) {
            s  += __shfl_xor_sync(0xFFFFFFFFu, s,  o);
            ss += __shfl_xor_sync(0xFFFFFFFFu, ss, o);
        }
        if (l == 0) { rs[0] = s; rq[0] = ss; }
    }
    __syncthreads();
    float mu   = rs[0] * (1.0f / DIMD);
    float var  = rq[0] * (1.0f / DIMD) - mu * mu;
    float rstd = rsqrtf(var + 1e-5f);
    float4 g4 = reinterpret_cast<const float4*>(gamma)[tid];
    float4 b4 = reinterpret_cast<const float4*>(beta)[tid];
    float4 o4;
    o4.x = (v.x - mu) * rstd * g4.x + b4.x;
    o4.y = (v.y - mu) * rstd * g4.y + b4.y;
    o4.z = (v.z - mu) * rstd * g4.z + b4.z;
    o4.w = (v.w - mu) * rstd * g4.w + b4.w;
    reinterpret_cast<float4*>(out + (size_t)row * DIMD)[tid] = o4;
}

// ---------------------------------------------------------------------------
// SGEMM: C[M,Nn] = A[M,K] @ B[K,Nn]; BM=BN=128, BK=16, 256 thr, 8x8/thread
// Requires M%128==0, Nn%128==0, K%16==0 (true for all uses here).
// ---------------------------------------------------------------------------
__global__ __launch_bounds__(256, 2)
void sgemm128(const float* __restrict__ A, const float* __restrict__ Bm,
              float* __restrict__ C, int M, int Nn, int K) {
    const int BM = 128, BN = 128, BK = 16;
    __shared__ float As[BK][BM + 4];
    __shared__ float Bs[BK][BN];
    int tid = threadIdx.x;
    int tr = tid >> 4;        // 0..15 -> rows tr*8..tr*8+7
    int tc = tid & 15;        // 0..15 -> cols tc*8..tc*8+7
    int bm = blockIdx.y, bn = blockIdx.x;
    const float* Ab = A  + (size_t)bm * BM * K;
    const float* Bb = Bm + (size_t)bn * BN;

    float acc[8][8];
    #pragma unroll
    for (int i = 0; i < 8; i++)
        #pragma unroll
        for (int j = 0; j < 8; j++) acc[i][j] = 0.f;

    for (int kt = 0; kt < K; kt += BK) {
        #pragma unroll
        for (int i = 0; i < 2; i++) {
            int idx = i * 256 + tid;            // 0..511
            int m   = idx >> 2;                 // 0..127
            int k4  = (idx & 3) << 2;           // 0,4,8,12
            float4 a4 = *reinterpret_cast<const float4*>(Ab + (size_t)m * K + kt + k4);
            As[k4 + 0][m] = a4.x; As[k4 + 1][m] = a4.y;
            As[k4 + 2][m] = a4.z; As[k4 + 3][m] = a4.w;
        }
        #pragma unroll
        for (int i = 0; i < 2; i++) {
            int idx = i * 256 + tid;            // 0..511
            int k   = idx >> 5;                 // 0..15
            int n4  = (idx & 31) << 2;          // 0..124
            *reinterpret_cast<float4*>(&Bs[k][n4]) =
                *reinterpret_cast<const float4*>(Bb + (size_t)(kt + k) * Nn + n4);
        }
        __syncthreads();
        #pragma unroll
        for (int k = 0; k < BK; k++) {
            float a[8], b[8];
            *reinterpret_cast<float4*>(a)     = *reinterpret_cast<float4*>(&As[k][tr * 8]);
            *reinterpret_cast<float4*>(a + 4) = *reinterpret_cast<float4*>(&As[k][tr * 8 + 4]);
            *reinterpret_cast<float4*>(b)     = *reinterpret_cast<float4*>(&Bs[k][tc * 8]);
            *reinterpret_cast<float4*>(b + 4) = *reinterpret_cast<float4*>(&Bs[k][tc * 8 + 4]);
            #pragma unroll
            for (int i = 0; i < 8; i++)
                #pragma unroll
                for (int j = 0; j < 8; j++) acc[i][j] += a[i] * b[j];
        }
        __syncthreads();
    }
    float* Cb = C + (size_t)(bm * BM + tr * 8) * Nn + bn * BN + tc * 8;
    #pragma unroll
    for (int i = 0; i < 8; i++) {
        *reinterpret_cast<float4*>(Cb + (size_t)i * Nn)     =
            make_float4(acc[i][0], acc[i][1], acc[i][2], acc[i][3]);
        *reinterpret_cast<float4*>(Cb + (size_t)i * Nn + 4) =
            make_float4(acc[i][4], acc[i][5], acc[i][6], acc[i][7]);
    }
}

// ---------------------------------------------------------------------------
// Flash attention fp32, causal. BQ=64 queries/block, BC=32 keys/iter.
// 256 threads: tq=tid/16 (4 q-rows each), tk=tid%16 (2 k-cols in S; 4 d-cols in PV).
// qkv layout per row (3072): [q(16h x 64) | k | v]
// ---------------------------------------------------------------------------
__global__ __launch_bounds__(256, 2)
void attn_kernel(const float* __restrict__ qkv, float* __restrict__ att) {
    const int BQ = 64, BC = 32;
    __shared__ float sQt[DH][BQ + 4];   // [64][68] transposed, pre-scaled
    __shared__ float sKt[DH][BC + 4];   // [64][36] transposed
    __shared__ float sV [BC][DH + 4];   // [32][68] natural
    __shared__ float sP [BQ][BC + 4];   // [64][36]

    int tid = threadIdx.x;
    int tq  = tid >> 4;     // 0..15
    int tk  = tid & 15;     // 0..15
    int qt  = blockIdx.x;   // 0..31
    int h   = blockIdx.y;
    int b   = blockIdx.z;

    const size_t rs = QKVW;
    const float* qbase = qkv + (size_t)b * SEQ * rs + h * DH;
    const float* kbase = qbase + INNER;
    const float* vbase = qbase + 2 * INNER;
    const float scale = 0.125f;   // 64^-0.5

    // Load Q tile (transposed + scaled)
    #pragma unroll
    for (int i = 0; i < 4; i++) {
        int idx = i * 256 + tid;        // 0..1023
        int q   = idx >> 4;             // 0..63
        int d4  = (idx & 15) << 2;      // 0..60
        float4 v = *reinterpret_cast<const float4*>(qbase + (size_t)(qt * BQ + q) * rs + d4);
        sQt[d4 + 0][q] = v.x * scale; sQt[d4 + 1][q] = v.y * scale;
        sQt[d4 + 2][q] = v.z * scale; sQt[d4 + 3][q] = v.w * scale;
    }

    float m[4], l[4], o[4][4];
    #pragma unroll
    for (int i = 0; i < 4; i++) {
        m[i] = -1e30f; l[i] = 0.f;
        #pragma unroll
        for (int j = 0; j < 4; j++) o[i][j] = 0.f;
    }

    int nkt = 2 * qt + 2;
    for (int kt = 0; kt < nkt; kt++) {
        __syncthreads();    // previous PV reads done before K/V overwrite
        #pragma unroll
        for (int i = 0; i < 2; i++) {
            int idx = i * 256 + tid;    // 0..511
            int n   = idx >> 4;         // 0..31
            int d4  = (idx & 15) << 2;
            float4 kv = *reinterpret_cast<const float4*>(kbase + (size_t)(kt * BC + n) * rs + d4);
            sKt[d4 + 0][n] = kv.x; sKt[d4 + 1][n] = kv.y;
            sKt[d4 + 2][n] = kv.z; sKt[d4 + 3][n] = kv.w;
            float4 vv = *reinterpret_cast<const float4*>(vbase + (size_t)(kt * BC + n) * rs + d4);
            *reinterpret_cast<float4*>(&sV[n][d4]) = vv;
        }
        __syncthreads();

        // S = (Q*scale) @ K^T for this thread's 4x2 patch
        float s[4][2] = {{0.f,0.f},{0.f,0.f},{0.f,0.f},{0.f,0.f}};
        #pragma unroll 16
        for (int d = 0; d < DH; d++) {
            float4 qv = *reinterpret_cast<float4*>(&sQt[d][tq * 4]);
            float2 kv = *reinterpret_cast<float2*>(&sKt[d][tk * 2]);
            s[0][0] += qv.x * kv.x; s[0][1] += qv.x * kv.y;
            s[1][0] += qv.y * kv.x; s[1][1] += qv.y * kv.y;
            s[2][0] += qv.z * kv.x; s[2][1] += qv.z * kv.y;
            s[3][0] += qv.w * kv.x; s[3][1] += qv.w * kv.y;
        }
        // Causal mask
        int q0 = qt * BQ + tq * 4;
        int k0 = kt * BC + tk * 2;
        #pragma unroll
        for (int i = 0; i < 4; i++)
            #pragma unroll
            for (int j = 0; j < 2; j++)
                if (k0 + j > q0 + i) s[i][j] = -1e30f;

        // Row max (over 2 local + 16 tk lanes within 16-lane shuffle group)
        float mt[4];
        #pragma unroll
        for (int i = 0; i < 4; i++) mt[i] = fmaxf(s[i][0], s[i][1]);
        #pragma unroll
        for (int off = 8; off > 0; off >>= 1)
            #pragma unroll
            for (int i = 0; i < 4; i++)
                mt[i] = fmaxf(mt[i], __shfl_xor_sync(0xFFFFFFFFu, mt[i], off));

        float rsum[4];
        #pragma unroll
        for (int i = 0; i < 4; i++) {
            float mn = fmaxf(m[i], mt[i]);
            float alpha = __expf(m[i] - mn);
            m[i] = mn;
            s[i][0] = __expf(s[i][0] - mn);
            s[i][1] = __expf(s[i][1] - mn);
            rsum[i] = s[i][0] + s[i][1];
            l[i] *= alpha;
            #pragma unroll
            for (int j = 0; j < 4; j++) o[i][j] *= alpha;
        }
        #pragma unroll
        for (int off = 8; off > 0; off >>= 1)
            #pragma unroll
            for (int i = 0; i < 4; i++)
                rsum[i] += __shfl_xor_sync(0xFFFFFFFFu, rsum[i], off);
        #pragma unroll
        for (int i = 0; i < 4; i++) l[i] += rsum[i];

        // Stash P
        #pragma unroll
        for (int i = 0; i < 4; i++) {
            sP[tq * 4 + i][tk * 2 + 0] = s[i][0];
            sP[tq * 4 + i][tk * 2 + 1] = s[i][1];
        }
        __syncthreads();

        // O += P @ V   (thread: 4 q-rows x 4 d-cols at tk*4)
        #pragma unroll 8
        for (int k = 0; k < BC; k++) {
            float4 vv = *reinterpret_cast<float4*>(&sV[k][tk * 4]);
            #pragma unroll
            for (int i = 0; i < 4; i++) {
                float p = sP[tq * 4 + i][k];
                o[i][0] += p * vv.x; o[i][1] += p * vv.y;
                o[i][2] += p * vv.z; o[i][3] += p * vv.w;
            }
        }
    }

    #pragma unroll
    for (int i = 0; i < 4; i++) {
        float inv = 1.f / l[i];
        int q = qt * BQ + tq * 4 + i;
        float* op = att + ((size_t)b * SEQ + q) * INNER + h * DH + tk * 4;
        *reinterpret_cast<float4*>(op) =
            make_float4(o[i][0] * inv, o[i][1] * inv, o[i][2] * inv, o[i][3] * inv);
    }
}

// ---------------------------------------------------------------------------
extern "C" void kernel_launch(void* const* d_in, const int* in_sizes, int n_in,
                              void* d_out, int out_size) {
    const float* x     = (const float*)d_in[0];
    const float* gamma = (const float*)d_in[1];
    const float* beta  = (const float*)d_in[2];
    const float* w_qkv = (const float*)d_in[3];
    const float* w_out = (const float*)d_in[4];
    float* out = (float*)d_out;

    float *xn, *qkv, *att;
    cudaGetSymbolAddress((void**)&xn,  g_xn);
    cudaGetSymbolAddress((void**)&qkv, g_qkv);
    cudaGetSymbolAddress((void**)&att, g_att);

    ln_kernel<<<ROWS, 256>>>(x, gamma, beta, xn);
    sgemm128<<<dim3(QKVW / 128, ROWS / 128), 256>>>(xn, w_qkv, qkv, ROWS, QKVW, DIMD);
    attn_kernel<<<dim3(SEQ / 64, HEADS, BATCH), 256>>>(qkv, att);
    sgemm128<<<dim3(DIMD / 128, ROWS / 128), 256>>>(att, w_out, out, ROWS, INNER, DIMD);
}

// round 3
// speedup vs baseline: 1.5946x; 1.5946x over previous
#include <cuda_runtime.h>
#include <math.h>
#include <cstdint>

#define DIMD   1024
#define HEADS  16
#define DH     64
#define INNER  1024
#define BATCH  4
#define SEQ    2048
#define ROWS   (BATCH*SEQ)      // 8192
#define QKVW   (3*INNER)        // 3072

// Scratch (device globals: allocation-free contract)
__device__ float g_xn   [ROWS*DIMD];        // 32 MB
__device__ float g_qkv  [ROWS*QKVW];        // 96 MB
__device__ float g_att  [ROWS*INNER];       // 32 MB
__device__ float g_wqkvT[QKVW*DIMD];        // 12 MB (tf32-rounded, [N][K])
__device__ float g_woutT[DIMD*INNER];       //  4 MB (tf32-rounded, [N][K])

__device__ __forceinline__ uint32_t cvt_tf32(float f) {
    uint32_t r;
    asm("cvt.rna.tf32.f32 %0, %1;" : "=r"(r) : "f"(f));
    return r;
}

__device__ __forceinline__ void mma_tf32_16x8x8(float* d, const uint32_t* a,
                                                const uint32_t* b) {
    asm volatile(
        "mma.sync.aligned.m16n8k8.row.col.f32.tf32.tf32.f32 "
        "{%0,%1,%2,%3}, {%4,%5,%6,%7}, {%8,%9}, {%0,%1,%2,%3};"
        : "+f"(d[0]), "+f"(d[1]), "+f"(d[2]), "+f"(d[3])
        : "r"(a[0]), "r"(a[1]), "r"(a[2]), "r"(a[3]), "r"(b[0]), "r"(b[1]));
}

// ===========================================================================
// LayerNorm: one block per row, 256 threads, float4
// ===========================================================================
__global__ void ln_kernel(const float* __restrict__ x,
                          const float* __restrict__ gamma,
                          const float* __restrict__ beta,
                          float* __restrict__ out) {
    int row = blockIdx.x;
    int tid = threadIdx.x;
    const float4* xr = reinterpret_cast<const float4*>(x + (size_t)row * DIMD);
    float4 v = xr[tid];
    float s  = v.x + v.y + v.z + v.w;
    float ss = v.x*v.x + v.y*v.y + v.z*v.z + v.w*v.w;
    #pragma unroll
    for (int o = 16; o > 0; o >>= 1) {
        s  += __shfl_xor_sync(0xFFFFFFFFu, s,  o);
        ss += __shfl_xor_sync(0xFFFFFFFFu, ss, o);
    }
    __shared__ float rs[8], rq[8];
    int w = tid >> 5, l = tid & 31;
    if (l == 0) { rs[w] = s; rq[w] = ss; }
    __syncthreads();
    if (w == 0) {
        s  = (l < 8) ? rs[l] : 0.f;
        ss = (l < 8) ? rq[l] : 0.f;
        #pragma unroll
        for (int o = 4; o > 0; o >>= 1) {
            s  += __shfl_xor_sync(0xFFFFFFFFu, s,  o);
            ss += __shfl_xor_sync(0xFFFFFFFFu, ss, o);
        }
        if (l == 0) { rs[0] = s; rq[0] = ss; }
    }
    __syncthreads();
    float mu   = rs[0] * (1.0f / DIMD);
    float var  = rq[0] * (1.0f / DIMD) - mu * mu;
    float rstd = rsqrtf(var + 1e-5f);
    float4 g4 = reinterpret_cast<const float4*>(gamma)[tid];
    float4 b4 = reinterpret_cast<const float4*>(beta)[tid];
    float4 o4;
    o4.x = (v.x - mu) * rstd * g4.x + b4.x;
    o4.y = (v.y - mu) * rstd * g4.y + b4.y;
    o4.z = (v.z - mu) * rstd * g4.z + b4.z;
    o4.w = (v.w - mu) * rstd * g4.w + b4.w;
    reinterpret_cast<float4*>(out + (size_t)row * DIMD)[tid] = o4;
}

// ===========================================================================
// Transpose + round-to-tf32: in [R][Cc] -> out [Cc][R]
// ===========================================================================
__global__ void transpose_cvt(const float* __restrict__ in, float* __restrict__ out,
                              int R, int Cc) {
    __shared__ float t[32][33];
    int c0 = blockIdx.x * 32, r0 = blockIdx.y * 32;
    int x = threadIdx.x, y = threadIdx.y;   // 32 x 8
    #pragma unroll
    for (int i = 0; i < 32; i += 8)
        t[y + i][x] = in[(size_t)(r0 + y + i) * Cc + c0 + x];
    __syncthreads();
    #pragma unroll
    for (int i = 0; i < 32; i += 8) {
        float v = t[x][y + i];
        out[(size_t)(c0 + y + i) * R + r0 + x] = __uint_as_float(cvt_tf32(v));
    }
}

// ===========================================================================
// tf32 mma.sync GEMM: C[M,Nn] = A[M,K] @ BT[Nn,K]^T
// CTA 128x128, BK=32, 256 threads (8 warps, 2x4), warp tile 64x32,
// register-prefetch of next gmem chunk, single smem buffer.
// ===========================================================================
#define GBK 32

__global__ __launch_bounds__(256)
void gemm_tf32(const float* __restrict__ A, const float* __restrict__ BT,
               float* __restrict__ C, int M, int Nn, int K) {
    __shared__ float As[128][GBK + 4];   // [m][k]
    __shared__ float Bs[128][GBK + 4];   // [n][k]

    int tid  = threadIdx.x;
    int lane = tid & 31;
    int wid  = tid >> 5;
    int wm   = wid >> 2;        // 0..1 -> m base wm*64
    int wn   = wid & 3;         // 0..3 -> n base wn*32

    const float* Ab = A  + (size_t)blockIdx.y * 128 * K;
    const float* Bb = BT + (size_t)blockIdx.x * 128 * K;

    // Staging indices: 1024 float4 per tile, 256 threads x 4 iters
    int sm  = tid >> 1;                  // used with iter: m = (i*256+tid)>>3
    (void)sm;

    float acc[4][4][4];
    #pragma unroll
    for (int i = 0; i < 4; i++)
        #pragma unroll
        for (int j = 0; j < 4; j++)
            #pragma unroll
            for (int k = 0; k < 4; k++) acc[i][j][k] = 0.f;

    const int nchunks = K / GBK;

    float4 pa[4], pb[4];
    // prefetch chunk 0
    #pragma unroll
    for (int i = 0; i < 4; i++) {
        int idx = i * 256 + tid;
        int m = idx >> 3, k4 = (idx & 7) << 2;
        pa[i] = *reinterpret_cast<const float4*>(Ab + (size_t)m * K + k4);
        pb[i] = *reinterpret_cast<const float4*>(Bb + (size_t)m * K + k4);
    }

    for (int c = 0; c < nchunks; c++) {
        __syncthreads();
        // store prefetched chunk to smem (A cvt to tf32; B pre-rounded)
        #pragma unroll
        for (int i = 0; i < 4; i++) {
            int idx = i * 256 + tid;
            int m = idx >> 3, k4 = (idx & 7) << 2;
            As[m][k4 + 0] = __uint_as_float(cvt_tf32(pa[i].x));
            As[m][k4 + 1] = __uint_as_float(cvt_tf32(pa[i].y));
            As[m][k4 + 2] = __uint_as_float(cvt_tf32(pa[i].z));
            As[m][k4 + 3] = __uint_as_float(cvt_tf32(pa[i].w));
            *reinterpret_cast<float4*>(&Bs[m][k4]) = pb[i];
        }
        __syncthreads();
        // prefetch next chunk
        if (c + 1 < nchunks) {
            const float* An = Ab + (c + 1) * GBK;
            const float* Bn = Bb + (c + 1) * GBK;
            #pragma unroll
            for (int i = 0; i < 4; i++) {
                int idx = i * 256 + tid;
                int m = idx >> 3, k4 = (idx & 7) << 2;
                pa[i] = *reinterpret_cast<const float4*>(An + (size_t)m * K + k4);
                pb[i] = *reinterpret_cast<const float4*>(Bn + (size_t)m * K + k4);
            }
        }
        // compute: 4 k-steps of 8
        int r  = lane >> 2;
        int cq = lane & 3;
        #pragma unroll
        for (int ks = 0; ks < 4; ks++) {
            uint32_t a[4][4], b[4][2];
            #pragma unroll
            for (int mt = 0; mt < 4; mt++) {
                const float* ap = &As[wm * 64 + mt * 16 + r][ks * 8 + cq];
                a[mt][0] = __float_as_uint(ap[0]);
                a[mt][1] = __float_as_uint(ap[8 * (GBK + 4)]);
                a[mt][2] = __float_as_uint(ap[4]);
                a[mt][3] = __float_as_uint(ap[8 * (GBK + 4) + 4]);
            }
            #pragma unroll
            for (int nt = 0; nt < 4; nt++) {
                const float* bp = &Bs[wn * 32 + nt * 8 + r][ks * 8 + cq];
                b[nt][0] = __float_as_uint(bp[0]);
                b[nt][1] = __float_as_uint(bp[4]);
            }
            #pragma unroll
            for (int mt = 0; mt < 4; mt++)
                #pragma unroll
                for (int nt = 0; nt < 4; nt++)
                    mma_tf32_16x8x8(acc[mt][nt], a[mt], b[nt]);
        }
    }

    // Epilogue: c0,c1 at (row, 2q),(row,2q+1); c2,c3 at (row+8, ...)
    int r  = lane >> 2;
    int cq = lane & 3;
    #pragma unroll
    for (int mt = 0; mt < 4; mt++) {
        int row0 = blockIdx.y * 128 + wm * 64 + mt * 16 + r;
        #pragma unroll
        for (int nt = 0; nt < 4; nt++) {
            int col0 = blockIdx.x * 128 + wn * 32 + nt * 8 + cq * 2;
            *reinterpret_cast<float2*>(C + (size_t)row0 * Nn + col0) =
                make_float2(acc[mt][nt][0], acc[mt][nt][1]);
            *reinterpret_cast<float2*>(C + (size_t)(row0 + 8) * Nn + col0) =
                make_float2(acc[mt][nt][2], acc[mt][nt][3]);
        }
    }
}

// ===========================================================================
// Flash attention fp32, causal. BQ=64, BC=32, 256 threads. (unchanged)
// ===========================================================================
__global__ __launch_bounds__(256, 2)
void attn_kernel(const float* __restrict__ qkv, float* __restrict__ att) {
    const int BQ = 64, BC = 32;
    __shared__ float sQt[DH][BQ + 4];
    __shared__ float sKt[DH][BC + 4];
    __shared__ float sV [BC][DH + 4];
    __shared__ float sP [BQ][BC + 4];

    int tid = threadIdx.x;
    int tq  = tid >> 4;
    int tk  = tid & 15;
    int qt  = blockIdx.x;
    int h   = blockIdx.y;
    int b   = blockIdx.z;

    const size_t rs = QKVW;
    const float* qbase = qkv + (size_t)b * SEQ * rs + h * DH;
    const float* kbase = qbase + INNER;
    const float* vbase = qbase + 2 * INNER;
    const float scale = 0.125f;

    #pragma unroll
    for (int i = 0; i < 4; i++) {
        int idx = i * 256 + tid;
        int q   = idx >> 4;
        int d4  = (idx & 15) << 2;
        float4 v = *reinterpret_cast<const float4*>(qbase + (size_t)(qt * BQ + q) * rs + d4);
        sQt[d4 + 0][q] = v.x * scale; sQt[d4 + 1][q] = v.y * scale;
        sQt[d4 + 2][q] = v.z * scale; sQt[d4 + 3][q] = v.w * scale;
    }

    float m[4], l[4], o[4][4];
    #pragma unroll
    for (int i = 0; i < 4; i++) {
        m[i] = -1e30f; l[i] = 0.f;
        #pragma unroll
        for (int j = 0; j < 4; j++) o[i][j] = 0.f;
    }

    int nkt = 2 * qt + 2;
    for (int kt = 0; kt < nkt; kt++) {
        __syncthreads();
        #pragma unroll
        for (int i = 0; i < 2; i++) {
            int idx = i * 256 + tid;
            int n   = idx >> 4;
            int d4  = (idx & 15) << 2;
            float4 kv = *reinterpret_cast<const float4*>(kbase + (size_t)(kt * BC + n) * rs + d4);
            sKt[d4 + 0][n] = kv.x; sKt[d4 + 1][n] = kv.y;
            sKt[d4 + 2][n] = kv.z; sKt[d4 + 3][n] = kv.w;
            float4 vv = *reinterpret_cast<const float4*>(vbase + (size_t)(kt * BC + n) * rs + d4);
            *reinterpret_cast<float4*>(&sV[n][d4]) = vv;
        }
        __syncthreads();

        float s[4][2] = {{0.f,0.f},{0.f,0.f},{0.f,0.f},{0.f,0.f}};
        #pragma unroll 16
        for (int d = 0; d < DH; d++) {
            float4 qv = *reinterpret_cast<float4*>(&sQt[d][tq * 4]);
            float2 kv = *reinterpret_cast<float2*>(&sKt[d][tk * 2]);
            s[0][0] += qv.x * kv.x; s[0][1] += qv.x * kv.y;
            s[1][0] += qv.y * kv.x; s[1][1] += qv.y * kv.y;
            s[2][0] += qv.z * kv.x; s[2][1] += qv.z * kv.y;
            s[3][0] += qv.w * kv.x; s[3][1] += qv.w * kv.y;
        }
        int q0 = qt * BQ + tq * 4;
        int k0 = kt * BC + tk * 2;
        #pragma unroll
        for (int i = 0; i < 4; i++)
            #pragma unroll
            for (int j = 0; j < 2; j++)
                if (k0 + j > q0 + i) s[i][j] = -1e30f;

        float mt[4];
        #pragma unroll
        for (int i = 0; i < 4; i++) mt[i] = fmaxf(s[i][0], s[i][1]);
        #pragma unroll
        for (int off = 8; off > 0; off >>= 1)
            #pragma unroll
            for (int i = 0; i < 4; i++)
                mt[i] = fmaxf(mt[i], __shfl_xor_sync(0xFFFFFFFFu, mt[i], off));

        float rsum[4];
        #pragma unroll
        for (int i = 0; i < 4; i++) {
            float mn = fmaxf(m[i], mt[i]);
            float alpha = __expf(m[i] - mn);
            m[i] = mn;
            s[i][0] = __expf(s[i][0] - mn);
            s[i][1] = __expf(s[i][1] - mn);
            rsum[i] = s[i][0] + s[i][1];
            l[i] *= alpha;
            #pragma unroll
            for (int j = 0; j < 4; j++) o[i][j] *= alpha;
        }
        #pragma unroll
        for (int off = 8; off > 0; off >>= 1)
            #pragma unroll
            for (int i = 0; i < 4; i++)
                rsum[i] += __shfl_xor_sync(0xFFFFFFFFu, rsum[i], off);
        #pragma unroll
        for (int i = 0; i < 4; i++) l[i] += rsum[i];

        #pragma unroll
        for (int i = 0; i < 4; i++) {
            sP[tq * 4 + i][tk * 2 + 0] = s[i][0];
            sP[tq * 4 + i][tk * 2 + 1] = s[i][1];
        }
        __syncthreads();

        #pragma unroll 8
        for (int k = 0; k < BC; k++) {
            float4 vv = *reinterpret_cast<float4*>(&sV[k][tk * 4]);
            #pragma unroll
            for (int i = 0; i < 4; i++) {
                float p = sP[tq * 4 + i][k];
                o[i][0] += p * vv.x; o[i][1] += p * vv.y;
                o[i][2] += p * vv.z; o[i][3] += p * vv.w;
            }
        }
    }

    #pragma unroll
    for (int i = 0; i < 4; i++) {
        float inv = 1.f / l[i];
        int q = qt * BQ + tq * 4 + i;
        float* op = att + ((size_t)b * SEQ + q) * INNER + h * DH + tk * 4;
        *reinterpret_cast<float4*>(op) =
            make_float4(o[i][0] * inv, o[i][1] * inv, o[i][2] * inv, o[i][3] * inv);
    }
}

// ===========================================================================
extern "C" void kernel_launch(void* const* d_in, const int* in_sizes, int n_in,
                              void* d_out, int out_size) {
    const float* x     = (const float*)d_in[0];
    const float* gamma = (const float*)d_in[1];
    const float* beta  = (const float*)d_in[2];
    const float* w_qkv = (const float*)d_in[3];
    const float* w_out = (const float*)d_in[4];
    float* out = (float*)d_out;

    float *xn, *qkv, *att, *wqkvT, *woutT;
    cudaGetSymbolAddress((void**)&xn,    g_xn);
    cudaGetSymbolAddress((void**)&qkv,   g_qkv);
    cudaGetSymbolAddress((void**)&att,   g_att);
    cudaGetSymbolAddress((void**)&wqkvT, g_wqkvT);
    cudaGetSymbolAddress((void**)&woutT, g_woutT);

    ln_kernel<<<ROWS, 256>>>(x, gamma, beta, xn);
    transpose_cvt<<<dim3(QKVW / 32, DIMD / 32), dim3(32, 8)>>>(w_qkv, wqkvT, DIMD, QKVW);
    transpose_cvt<<<dim3(DIMD / 32, INNER / 32), dim3(32, 8)>>>(w_out, woutT, INNER, DIMD);
    gemm_tf32<<<dim3(QKVW / 128, ROWS / 128), 256>>>(xn, wqkvT, qkv, ROWS, QKVW, DIMD);
    attn_kernel<<<dim3(SEQ / 64, HEADS, BATCH), 256>>>(qkv, att);
    gemm_tf32<<<dim3(DIMD / 128, ROWS / 128), 256>>>(att, woutT, out, ROWS, DIMD, INNER);
}

// round 4
// speedup vs baseline: 3.1401x; 1.9692x over previous
#include <cuda_runtime.h>
#include <math.h>
#include <cstdint>

#define DIMD   1024
#define HEADS  16
#define DH     64
#define INNER  1024
#define BATCH  4
#define SEQ    2048
#define ROWS   (BATCH*SEQ)      // 8192
#define QKVW   (3*INNER)        // 3072

// Scratch (device globals: allocation-free contract)
__device__ float g_xn   [ROWS*DIMD];        // 32 MB
__device__ float g_qkv  [ROWS*QKVW];        // 96 MB
__device__ float g_att  [ROWS*INNER];       // 32 MB
__device__ float g_wqkvT[QKVW*DIMD];        // 12 MB (tf32-rounded, [N][K])
__device__ float g_woutT[DIMD*INNER];       //  4 MB (tf32-rounded, [N][K])

__device__ __forceinline__ uint32_t cvt_tf32(float f) {
    uint32_t r;
    asm("cvt.rna.tf32.f32 %0, %1;" : "=r"(r) : "f"(f));
    return r;
}
__device__ __forceinline__ float cvt_tf32_f(float f) {
    return __uint_as_float(cvt_tf32(f));
}

__device__ __forceinline__ void mma_tf32_16x8x8(float* d, const uint32_t* a,
                                                const uint32_t* b) {
    asm volatile(
        "mma.sync.aligned.m16n8k8.row.col.f32.tf32.tf32.f32 "
        "{%0,%1,%2,%3}, {%4,%5,%6,%7}, {%8,%9}, {%0,%1,%2,%3};"
        : "+f"(d[0]), "+f"(d[1]), "+f"(d[2]), "+f"(d[3])
        : "r"(a[0]), "r"(a[1]), "r"(a[2]), "r"(a[3]), "r"(b[0]), "r"(b[1]));
}

// ===========================================================================
// LayerNorm: one block per row, 256 threads, float4
// ===========================================================================
__global__ void ln_kernel(const float* __restrict__ x,
                          const float* __restrict__ gamma,
                          const float* __restrict__ beta,
                          float* __restrict__ out) {
    int row = blockIdx.x;
    int tid = threadIdx.x;
    const float4* xr = reinterpret_cast<const float4*>(x + (size_t)row * DIMD);
    float4 v = xr[tid];
    float s  = v.x + v.y + v.z + v.w;
    float ss = v.x*v.x + v.y*v.y + v.z*v.z + v.w*v.w;
    #pragma unroll
    for (int o = 16; o > 0; o >>= 1) {
        s  += __shfl_xor_sync(0xFFFFFFFFu, s,  o);
        ss += __shfl_xor_sync(0xFFFFFFFFu, ss, o);
    }
    __shared__ float rs[8], rq[8];
    int w = tid >> 5, l = tid & 31;
    if (l == 0) { rs[w] = s; rq[w] = ss; }
    __syncthreads();
    if (w == 0) {
        s  = (l < 8) ? rs[l] : 0.f;
        ss = (l < 8) ? rq[l] : 0.f;
        #pragma unroll
        for (int o = 4; o > 0; o >>= 1) {
            s  += __shfl_xor_sync(0xFFFFFFFFu, s,  o);
            ss += __shfl_xor_sync(0xFFFFFFFFu, ss, o);
        }
        if (l == 0) { rs[0] = s; rq[0] = ss; }
    }
    __syncthreads();
    float mu   = rs[0] * (1.0f / DIMD);
    float var  = rq[0] * (1.0f / DIMD) - mu * mu;
    float rstd = rsqrtf(var + 1e-5f);
    float4 g4 = reinterpret_cast<const float4*>(gamma)[tid];
    float4 b4 = reinterpret_cast<const float4*>(beta)[tid];
    float4 o4;
    o4.x = (v.x - mu) * rstd * g4.x + b4.x;
    o4.y = (v.y - mu) * rstd * g4.y + b4.y;
    o4.z = (v.z - mu) * rstd * g4.z + b4.z;
    o4.w = (v.w - mu) * rstd * g4.w + b4.w;
    reinterpret_cast<float4*>(out + (size_t)row * DIMD)[tid] = o4;
}

// ===========================================================================
// Transpose + round-to-tf32: in [R][Cc] -> out [Cc][R]
// ===========================================================================
__global__ void transpose_cvt(const float* __restrict__ in, float* __restrict__ out,
                              int R, int Cc) {
    __shared__ float t[32][33];
    int c0 = blockIdx.x * 32, r0 = blockIdx.y * 32;
    int x = threadIdx.x, y = threadIdx.y;   // 32 x 8
    #pragma unroll
    for (int i = 0; i < 32; i += 8)
        t[y + i][x] = in[(size_t)(r0 + y + i) * Cc + c0 + x];
    __syncthreads();
    #pragma unroll
    for (int i = 0; i < 32; i += 8) {
        float v = t[x][y + i];
        out[(size_t)(c0 + y + i) * R + r0 + x] = cvt_tf32_f(v);
    }
}

// ===========================================================================
// tf32 mma.sync GEMM: C[M,Nn] = A[M,K] @ BT[Nn,K]^T  (unchanged from R3)
// ===========================================================================
#define GBK 32

__global__ __launch_bounds__(256)
void gemm_tf32(const float* __restrict__ A, const float* __restrict__ BT,
               float* __restrict__ C, int M, int Nn, int K) {
    __shared__ float As[128][GBK + 4];
    __shared__ float Bs[128][GBK + 4];

    int tid  = threadIdx.x;
    int lane = tid & 31;
    int wid  = tid >> 5;
    int wm   = wid >> 2;
    int wn   = wid & 3;

    const float* Ab = A  + (size_t)blockIdx.y * 128 * K;
    const float* Bb = BT + (size_t)blockIdx.x * 128 * K;

    float acc[4][4][4];
    #pragma unroll
    for (int i = 0; i < 4; i++)
        #pragma unroll
        for (int j = 0; j < 4; j++)
            #pragma unroll
            for (int k = 0; k < 4; k++) acc[i][j][k] = 0.f;

    const int nchunks = K / GBK;

    float4 pa[4], pb[4];
    #pragma unroll
    for (int i = 0; i < 4; i++) {
        int idx = i * 256 + tid;
        int m = idx >> 3, k4 = (idx & 7) << 2;
        pa[i] = *reinterpret_cast<const float4*>(Ab + (size_t)m * K + k4);
        pb[i] = *reinterpret_cast<const float4*>(Bb + (size_t)m * K + k4);
    }

    for (int c = 0; c < nchunks; c++) {
        __syncthreads();
        #pragma unroll
        for (int i = 0; i < 4; i++) {
            int idx = i * 256 + tid;
            int m = idx >> 3, k4 = (idx & 7) << 2;
            As[m][k4 + 0] = cvt_tf32_f(pa[i].x);
            As[m][k4 + 1] = cvt_tf32_f(pa[i].y);
            As[m][k4 + 2] = cvt_tf32_f(pa[i].z);
            As[m][k4 + 3] = cvt_tf32_f(pa[i].w);
            *reinterpret_cast<float4*>(&Bs[m][k4]) = pb[i];
        }
        __syncthreads();
        if (c + 1 < nchunks) {
            const float* An = Ab + (c + 1) * GBK;
            const float* Bn = Bb + (c + 1) * GBK;
            #pragma unroll
            for (int i = 0; i < 4; i++) {
                int idx = i * 256 + tid;
                int m = idx >> 3, k4 = (idx & 7) << 2;
                pa[i] = *reinterpret_cast<const float4*>(An + (size_t)m * K + k4);
                pb[i] = *reinterpret_cast<const float4*>(Bn + (size_t)m * K + k4);
            }
        }
        int r  = lane >> 2;
        int cq = lane & 3;
        #pragma unroll
        for (int ks = 0; ks < 4; ks++) {
            uint32_t a[4][4], b[4][2];
            #pragma unroll
            for (int mt = 0; mt < 4; mt++) {
                const float* ap = &As[wm * 64 + mt * 16 + r][ks * 8 + cq];
                a[mt][0] = __float_as_uint(ap[0]);
                a[mt][1] = __float_as_uint(ap[8 * (GBK + 4)]);
                a[mt][2] = __float_as_uint(ap[4]);
                a[mt][3] = __float_as_uint(ap[8 * (GBK + 4) + 4]);
            }
            #pragma unroll
            for (int nt = 0; nt < 4; nt++) {
                const float* bp = &Bs[wn * 32 + nt * 8 + r][ks * 8 + cq];
                b[nt][0] = __float_as_uint(bp[0]);
                b[nt][1] = __float_as_uint(bp[4]);
            }
            #pragma unroll
            for (int mt = 0; mt < 4; mt++)
                #pragma unroll
                for (int nt = 0; nt < 4; nt++)
                    mma_tf32_16x8x8(acc[mt][nt], a[mt], b[nt]);
        }
    }

    int r  = lane >> 2;
    int cq = lane & 3;
    #pragma unroll
    for (int mt = 0; mt < 4; mt++) {
        int row0 = blockIdx.y * 128 + wm * 64 + mt * 16 + r;
        #pragma unroll
        for (int nt = 0; nt < 4; nt++) {
            int col0 = blockIdx.x * 128 + wn * 32 + nt * 8 + cq * 2;
            *reinterpret_cast<float2*>(C + (size_t)row0 * Nn + col0) =
                make_float2(acc[mt][nt][0], acc[mt][nt][1]);
            *reinterpret_cast<float2*>(C + (size_t)(row0 + 8) * Nn + col0) =
                make_float2(acc[mt][nt][2], acc[mt][nt][3]);
        }
    }
}

// ===========================================================================
// Flash attention via tf32 mma.sync. One block = (b, h), BQ=128, BC=64.
// 8 warps x 16 q-rows. Q frags in regs; K [kv][d]; V transposed [d][kv];
// P routed through warp-private smem. Online softmax on accumulator layout.
// ===========================================================================
#define APAD 68           // row stride (floats) for all attn smem tiles
#define ASM_K  0
#define ASM_VT (64 * APAD)
#define ASM_P  (2 * 64 * APAD)
#define ATTN_SMEM ((2 * 64 * APAD + 128 * APAD) * 4)   // 69632 B

__global__ __launch_bounds__(256)
void attn_mma(const float* __restrict__ qkv, float* __restrict__ att) {
    extern __shared__ float sm[];
    float* sK  = sm + ASM_K;
    float* sVt = sm + ASM_VT;
    float* sP  = sm + ASM_P;

    int tid = threadIdx.x, lane = tid & 31, wid = tid >> 5;
    int r = lane >> 2, cq = lane & 3;
    int qt = blockIdx.x, h = blockIdx.y, b = blockIdx.z;
    int q0 = qt * 128;

    const float* qbase = qkv + (size_t)b * SEQ * QKVW + h * DH;
    const float* kbase = qbase + INNER;
    const float* vbase = qbase + 2 * INNER;

    // ---- Stage Q (scaled, tf32) through sP, pull fragments to registers
    #pragma unroll
    for (int i = 0; i < 8; i++) {
        int idx = i * 256 + tid;
        int row = idx >> 4, d4 = (idx & 15) << 2;
        float4 v = *reinterpret_cast<const float4*>(qbase + (size_t)(q0 + row) * QKVW + d4);
        float* p = &sP[row * APAD + d4];
        p[0] = cvt_tf32_f(v.x * 0.125f);
        p[1] = cvt_tf32_f(v.y * 0.125f);
        p[2] = cvt_tf32_f(v.z * 0.125f);
        p[3] = cvt_tf32_f(v.w * 0.125f);
    }
    __syncthreads();
    uint32_t qf[8][4];
    #pragma unroll
    for (int kt = 0; kt < 8; kt++) {
        const float* p = &sP[(wid * 16 + r) * APAD + kt * 8 + cq];
        qf[kt][0] = __float_as_uint(p[0]);
        qf[kt][1] = __float_as_uint(p[8 * APAD]);
        qf[kt][2] = __float_as_uint(p[4]);
        qf[kt][3] = __float_as_uint(p[8 * APAD + 4]);
    }

    float m0 = -1e30f, m1 = -1e30f, l0 = 0.f, l1 = 0.f;
    float o[8][4];
    #pragma unroll
    for (int nt = 0; nt < 8; nt++)
        #pragma unroll
        for (int j = 0; j < 4; j++) o[nt][j] = 0.f;

    int nchunk = 2 * qt + 2;
    for (int c = 0; c < nchunk; c++) {
        __syncthreads();
        // stage K [kv][d] and V transposed [d][kv], tf32-rounded
        #pragma unroll
        for (int i = 0; i < 4; i++) {
            int idx = i * 256 + tid;
            int row = idx >> 4, d4 = (idx & 15) << 2;
            const float* krow = kbase + (size_t)(c * 64 + row) * QKVW + d4;
            float4 kv = *reinterpret_cast<const float4*>(krow);
            float* kp = &sK[row * APAD + d4];
            kp[0] = cvt_tf32_f(kv.x); kp[1] = cvt_tf32_f(kv.y);
            kp[2] = cvt_tf32_f(kv.z); kp[3] = cvt_tf32_f(kv.w);
            const float* vrow = vbase + (size_t)(c * 64 + row) * QKVW + d4;
            float4 vv = *reinterpret_cast<const float4*>(vrow);
            sVt[(d4 + 0) * APAD + row] = cvt_tf32_f(vv.x);
            sVt[(d4 + 1) * APAD + row] = cvt_tf32_f(vv.y);
            sVt[(d4 + 2) * APAD + row] = cvt_tf32_f(vv.z);
            sVt[(d4 + 3) * APAD + row] = cvt_tf32_f(vv.w);
        }
        __syncthreads();

        int wrow0 = q0 + wid * 16;               // warp's min q row
        if (wrow0 + 15 < c * 64) continue;       // fully masked chunk for this warp

        // ---- S = Q @ K^T
        float s[8][4];
        #pragma unroll
        for (int nt = 0; nt < 8; nt++)
            #pragma unroll
            for (int j = 0; j < 4; j++) s[nt][j] = 0.f;
        #pragma unroll
        for (int kt = 0; kt < 8; kt++) {
            uint32_t bf[8][2];
            #pragma unroll
            for (int nt = 0; nt < 8; nt++) {
                const float* kp = &sK[(nt * 8 + r) * APAD + kt * 8 + cq];
                bf[nt][0] = __float_as_uint(kp[0]);
                bf[nt][1] = __float_as_uint(kp[4]);
            }
            #pragma unroll
            for (int nt = 0; nt < 8; nt++)
                mma_tf32_16x8x8(s[nt], qf[kt], bf[nt]);
        }

        // ---- causal mask (only when chunk overlaps this warp's rows)
        if (c * 64 + 63 > wrow0) {
            int row_a = wrow0 + r, row_b = wrow0 + r + 8;
            #pragma unroll
            for (int nt = 0; nt < 8; nt++) {
                int col = c * 64 + nt * 8 + 2 * cq;
                if (col     > row_a) s[nt][0] = -1e30f;
                if (col + 1 > row_a) s[nt][1] = -1e30f;
                if (col     > row_b) s[nt][2] = -1e30f;
                if (col + 1 > row_b) s[nt][3] = -1e30f;
            }
        }

        // ---- online softmax (row stats across quad lanes)
        float mt0 = -1e30f, mt1 = -1e30f;
        #pragma unroll
        for (int nt = 0; nt < 8; nt++) {
            mt0 = fmaxf(mt0, fmaxf(s[nt][0], s[nt][1]));
            mt1 = fmaxf(mt1, fmaxf(s[nt][2], s[nt][3]));
        }
        mt0 = fmaxf(mt0, __shfl_xor_sync(0xFFFFFFFFu, mt0, 1));
        mt0 = fmaxf(mt0, __shfl_xor_sync(0xFFFFFFFFu, mt0, 2));
        mt1 = fmaxf(mt1, __shfl_xor_sync(0xFFFFFFFFu, mt1, 1));
        mt1 = fmaxf(mt1, __shfl_xor_sync(0xFFFFFFFFu, mt1, 2));

        float mn0 = fmaxf(m0, mt0), mn1 = fmaxf(m1, mt1);
        float a0 = __expf(m0 - mn0), a1 = __expf(m1 - mn1);
        m0 = mn0; m1 = mn1;
        float rs0 = 0.f, rs1 = 0.f;
        #pragma unroll
        for (int nt = 0; nt < 8; nt++) {
            s[nt][0] = __expf(s[nt][0] - mn0);
            s[nt][1] = __expf(s[nt][1] - mn0);
            s[nt][2] = __expf(s[nt][2] - mn1);
            s[nt][3] = __expf(s[nt][3] - mn1);
            rs0 += s[nt][0] + s[nt][1];
            rs1 += s[nt][2] + s[nt][3];
        }
        rs0 += __shfl_xor_sync(0xFFFFFFFFu, rs0, 1);
        rs0 += __shfl_xor_sync(0xFFFFFFFFu, rs0, 2);
        rs1 += __shfl_xor_sync(0xFFFFFFFFu, rs1, 1);
        rs1 += __shfl_xor_sync(0xFFFFFFFFu, rs1, 2);
        l0 = l0 * a0 + rs0;
        l1 = l1 * a1 + rs1;
        #pragma unroll
        for (int nt = 0; nt < 8; nt++) {
            o[nt][0] *= a0; o[nt][1] *= a0;
            o[nt][2] *= a1; o[nt][3] *= a1;
        }

        // ---- P -> warp-private smem (tf32)
        float* pr0 = &sP[(wid * 16 + r) * APAD];
        float* pr1 = &sP[(wid * 16 + r + 8) * APAD];
        #pragma unroll
        for (int nt = 0; nt < 8; nt++) {
            int col = nt * 8 + 2 * cq;
            pr0[col]     = cvt_tf32_f(s[nt][0]);
            pr0[col + 1] = cvt_tf32_f(s[nt][1]);
            pr1[col]     = cvt_tf32_f(s[nt][2]);
            pr1[col + 1] = cvt_tf32_f(s[nt][3]);
        }
        __syncwarp();

        // ---- O += P @ V
        #pragma unroll
        for (int kt = 0; kt < 8; kt++) {
            uint32_t pf[4];
            const float* pp = &sP[(wid * 16 + r) * APAD + kt * 8 + cq];
            pf[0] = __float_as_uint(pp[0]);
            pf[1] = __float_as_uint(pp[8 * APAD]);
            pf[2] = __float_as_uint(pp[4]);
            pf[3] = __float_as_uint(pp[8 * APAD + 4]);
            uint32_t bf[8][2];
            #pragma unroll
            for (int nt = 0; nt < 8; nt++) {
                const float* vp = &sVt[(nt * 8 + r) * APAD + kt * 8 + cq];
                bf[nt][0] = __float_as_uint(vp[0]);
                bf[nt][1] = __float_as_uint(vp[4]);
            }
            #pragma unroll
            for (int nt = 0; nt < 8; nt++)
                mma_tf32_16x8x8(o[nt], pf, bf[nt]);
        }
        __syncwarp();   // sP reads done before next chunk's (no-op safety)
    }

    // ---- epilogue
    float inv0 = 1.f / l0, inv1 = 1.f / l1;
    int row_a = q0 + wid * 16 + r, row_b = row_a + 8;
    #pragma unroll
    for (int nt = 0; nt < 8; nt++) {
        int col = h * DH + nt * 8 + 2 * cq;
        *reinterpret_cast<float2*>(att + ((size_t)b * SEQ + row_a) * INNER + col) =
            make_float2(o[nt][0] * inv0, o[nt][1] * inv0);
        *reinterpret_cast<float2*>(att + ((size_t)b * SEQ + row_b) * INNER + col) =
            make_float2(o[nt][2] * inv1, o[nt][3] * inv1);
    }
}

// ===========================================================================
extern "C" void kernel_launch(void* const* d_in, const int* in_sizes, int n_in,
                              void* d_out, int out_size) {
    const float* x     = (const float*)d_in[0];
    const float* gamma = (const float*)d_in[1];
    const float* beta  = (const float*)d_in[2];
    const float* w_qkv = (const float*)d_in[3];
    const float* w_out = (const float*)d_in[4];
    float* out = (float*)d_out;

    float *xn, *qkv, *att, *wqkvT, *woutT;
    cudaGetSymbolAddress((void**)&xn,    g_xn);
    cudaGetSymbolAddress((void**)&qkv,   g_qkv);
    cudaGetSymbolAddress((void**)&att,   g_att);
    cudaGetSymbolAddress((void**)&wqkvT, g_wqkvT);
    cudaGetSymbolAddress((void**)&woutT, g_woutT);

    cudaFuncSetAttribute(attn_mma, cudaFuncAttributeMaxDynamicSharedMemorySize, ATTN_SMEM);

    ln_kernel<<<ROWS, 256>>>(x, gamma, beta, xn);
    transpose_cvt<<<dim3(QKVW / 32, DIMD / 32), dim3(32, 8)>>>(w_qkv, wqkvT, DIMD, QKVW);
    transpose_cvt<<<dim3(DIMD / 32, INNER / 32), dim3(32, 8)>>>(w_out, woutT, INNER, DIMD);
    gemm_tf32<<<dim3(QKVW / 128, ROWS / 128), 256>>>(xn, wqkvT, qkv, ROWS, QKVW, DIMD);
    attn_mma<<<dim3(SEQ / 128, HEADS, BATCH), 256, ATTN_SMEM>>>(qkv, att);
    gemm_tf32<<<dim3(DIMD / 128, ROWS / 128), 256>>>(att, woutT, out, ROWS, DIMD, INNER);
}

// round 5
// speedup vs baseline: 3.1703x; 1.0096x over previous
#include <cuda_runtime.h>
#include <math.h>
#include <cstdint>

#define DIMD   1024
#define HEADS  16
#define DH     64
#define INNER  1024
#define BATCH  4
#define SEQ    2048
#define ROWS   (BATCH*SEQ)      // 8192
#define QKVW   (3*INNER)        // 3072

// Scratch (device globals: allocation-free contract)
__device__ float g_xn   [ROWS*DIMD];        // tf32-rounded LN output
__device__ float g_qkv  [ROWS*QKVW];        // tf32-rounded QKV
__device__ float g_att  [ROWS*INNER];       // tf32-rounded attention output
__device__ float g_wqkvT[QKVW*DIMD];        // tf32-rounded, [N][K]
__device__ float g_woutT[DIMD*INNER];       // tf32-rounded, [N][K]

__device__ __forceinline__ uint32_t cvt_tf32(float f) {
    uint32_t r;
    asm("cvt.rna.tf32.f32 %0, %1;" : "=r"(r) : "f"(f));
    return r;
}
__device__ __forceinline__ float cvt_tf32_f(float f) {
    return __uint_as_float(cvt_tf32(f));
}

__device__ __forceinline__ void mma_tf32_16x8x8(float* d, const uint32_t* a,
                                                const uint32_t* b) {
    asm volatile(
        "mma.sync.aligned.m16n8k8.row.col.f32.tf32.tf32.f32 "
        "{%0,%1,%2,%3}, {%4,%5,%6,%7}, {%8,%9}, {%0,%1,%2,%3};"
        : "+f"(d[0]), "+f"(d[1]), "+f"(d[2]), "+f"(d[3])
        : "r"(a[0]), "r"(a[1]), "r"(a[2]), "r"(a[3]), "r"(b[0]), "r"(b[1]));
}

__device__ __forceinline__ void cp_async16(uint32_t smem_dst, const void* gmem_src) {
    asm volatile("cp.async.cg.shared.global [%0], [%1], 16;" :: "r"(smem_dst), "l"(gmem_src));
}
#define CP_COMMIT() asm volatile("cp.async.commit_group;" ::: "memory")
#define CP_WAIT(n)  asm volatile("cp.async.wait_group %0;" :: "n"(n) : "memory")

// ===========================================================================
// LayerNorm: one block per row, 256 threads, float4; OUTPUT tf32-rounded.
// ===========================================================================
__global__ void ln_kernel(const float* __restrict__ x,
                          const float* __restrict__ gamma,
                          const float* __restrict__ beta,
                          float* __restrict__ out) {
    int row = blockIdx.x;
    int tid = threadIdx.x;
    const float4* xr = reinterpret_cast<const float4*>(x + (size_t)row * DIMD);
    float4 v = xr[tid];
    float s  = v.x + v.y + v.z + v.w;
    float ss = v.x*v.x + v.y*v.y + v.z*v.z + v.w*v.w;
    #pragma unroll
    for (int o = 16; o > 0; o >>= 1) {
        s  += __shfl_xor_sync(0xFFFFFFFFu, s,  o);
        ss += __shfl_xor_sync(0xFFFFFFFFu, ss, o);
    }
    __shared__ float rs[8], rq[8];
    int w = tid >> 5, l = tid & 31;
    if (l == 0) { rs[w] = s; rq[w] = ss; }
    __syncthreads();
    if (w == 0) {
        s  = (l < 8) ? rs[l] : 0.f;
        ss = (l < 8) ? rq[l] : 0.f;
        #pragma unroll
        for (int o = 4; o > 0; o >>= 1) {
            s  += __shfl_xor_sync(0xFFFFFFFFu, s,  o);
            ss += __shfl_xor_sync(0xFFFFFFFFu, ss, o);
        }
        if (l == 0) { rs[0] = s; rq[0] = ss; }
    }
    __syncthreads();
    float mu   = rs[0] * (1.0f / DIMD);
    float var  = rq[0] * (1.0f / DIMD) - mu * mu;
    float rstd = rsqrtf(var + 1e-5f);
    float4 g4 = reinterpret_cast<const float4*>(gamma)[tid];
    float4 b4 = reinterpret_cast<const float4*>(beta)[tid];
    float4 o4;
    o4.x = cvt_tf32_f((v.x - mu) * rstd * g4.x + b4.x);
    o4.y = cvt_tf32_f((v.y - mu) * rstd * g4.y + b4.y);
    o4.z = cvt_tf32_f((v.z - mu) * rstd * g4.z + b4.z);
    o4.w = cvt_tf32_f((v.w - mu) * rstd * g4.w + b4.w);
    reinterpret_cast<float4*>(out + (size_t)row * DIMD)[tid] = o4;
}

// ===========================================================================
// Transpose + round-to-tf32: in [R][Cc] -> out [Cc][R]
// ===========================================================================
__global__ void transpose_cvt(const float* __restrict__ in, float* __restrict__ out,
                              int R, int Cc) {
    __shared__ float t[32][33];
    int c0 = blockIdx.x * 32, r0 = blockIdx.y * 32;
    int x = threadIdx.x, y = threadIdx.y;   // 32 x 8
    #pragma unroll
    for (int i = 0; i < 32; i += 8)
        t[y + i][x] = in[(size_t)(r0 + y + i) * Cc + c0 + x];
    __syncthreads();
    #pragma unroll
    for (int i = 0; i < 32; i += 8) {
        float v = t[x][y + i];
        out[(size_t)(c0 + y + i) * R + r0 + x] = cvt_tf32_f(v);
    }
}

// ===========================================================================
// tf32 mma.sync GEMM, cp.async 2-stage pipeline.
// C[M,Nn] = A[M,K] @ BT[Nn,K]^T. A and BT are PRE-ROUNDED to tf32.
// CTA 128x128, BK=32, 256 threads (8 warps, 2x4), warp tile 64x32.
// ROUND_OUT: round C to tf32 (for intermediates feeding later tf32 MMAs).
// ===========================================================================
#define GBK   32
#define GSTR  (GBK + 4)                 // 36 floats row stride
#define GTILE (128 * GSTR)              // floats per tile
#define GEMM_SMEM (4 * GTILE * 4)       // 2 stages x (A+B) = 73728 B

template <bool ROUND_OUT>
__global__ __launch_bounds__(256, 2)
void gemm_tf32(const float* __restrict__ A, const float* __restrict__ BT,
               float* __restrict__ C, int M, int Nn, int K) {
    extern __shared__ float sm[];

    int tid  = threadIdx.x;
    int lane = tid & 31;
    int wid  = tid >> 5;
    int wm   = wid >> 2;
    int wn   = wid & 3;

    const float* Ab = A  + (size_t)blockIdx.y * 128 * K;
    const float* Bb = BT + (size_t)blockIdx.x * 128 * K;

    // per-thread staging coords: 4 x 16B for A, 4 for B
    int smA = tid >> 3;                  // unused placeholder removed below
    (void)smA;

    float acc[4][4][4];
    #pragma unroll
    for (int i = 0; i < 4; i++)
        #pragma unroll
        for (int j = 0; j < 4; j++)
            #pragma unroll
            for (int k = 0; k < 4; k++) acc[i][j][k] = 0.f;

    const int nchunks = K / GBK;
    uint32_t smbase = (uint32_t)__cvta_generic_to_shared(sm);

    auto stage = [&](int c) {
        int buf = c & 1;
        uint32_t sA = smbase + (buf * GTILE) * 4;
        uint32_t sB = smbase + ((2 + buf) * GTILE) * 4;
        const float* Ac = Ab + c * GBK;
        const float* Bc = Bb + c * GBK;
        #pragma unroll
        for (int i = 0; i < 4; i++) {
            int idx = i * 256 + tid;
            int m = idx >> 3, k4 = (idx & 7) << 2;
            cp_async16(sA + (m * GSTR + k4) * 4, Ac + (size_t)m * K + k4);
            cp_async16(sB + (m * GSTR + k4) * 4, Bc + (size_t)m * K + k4);
        }
    };

    stage(0);
    CP_COMMIT();

    int r  = lane >> 2;
    int cq = lane & 3;

    for (int c = 0; c < nchunks; c++) {
        if (c + 1 < nchunks) {
            stage(c + 1);
            CP_COMMIT();
            CP_WAIT(1);
        } else {
            CP_WAIT(0);
        }
        __syncthreads();

        const float* As = sm + (c & 1) * GTILE;
        const float* Bs = sm + (2 + (c & 1)) * GTILE;

        #pragma unroll
        for (int ks = 0; ks < 4; ks++) {
            uint32_t a[4][4], b[4][2];
            #pragma unroll
            for (int mt = 0; mt < 4; mt++) {
                const float* ap = &As[(wm * 64 + mt * 16 + r) * GSTR + ks * 8 + cq];
                a[mt][0] = __float_as_uint(ap[0]);
                a[mt][1] = __float_as_uint(ap[8 * GSTR]);
                a[mt][2] = __float_as_uint(ap[4]);
                a[mt][3] = __float_as_uint(ap[8 * GSTR + 4]);
            }
            #pragma unroll
            for (int nt = 0; nt < 4; nt++) {
                const float* bp = &Bs[(wn * 32 + nt * 8 + r) * GSTR + ks * 8 + cq];
                b[nt][0] = __float_as_uint(bp[0]);
                b[nt][1] = __float_as_uint(bp[4]);
            }
            #pragma unroll
            for (int mt = 0; mt < 4; mt++)
                #pragma unroll
                for (int nt = 0; nt < 4; nt++)
                    mma_tf32_16x8x8(acc[mt][nt], a[mt], b[nt]);
        }
        __syncthreads();
    }

    #pragma unroll
    for (int mt = 0; mt < 4; mt++) {
        int row0 = blockIdx.y * 128 + wm * 64 + mt * 16 + r;
        #pragma unroll
        for (int nt = 0; nt < 4; nt++) {
            int col0 = blockIdx.x * 128 + wn * 32 + nt * 8 + cq * 2;
            float v00 = acc[mt][nt][0], v01 = acc[mt][nt][1];
            float v10 = acc[mt][nt][2], v11 = acc[mt][nt][3];
            if (ROUND_OUT) {
                v00 = cvt_tf32_f(v00); v01 = cvt_tf32_f(v01);
                v10 = cvt_tf32_f(v10); v11 = cvt_tf32_f(v11);
            }
            *reinterpret_cast<float2*>(C + (size_t)row0 * Nn + col0) = make_float2(v00, v01);
            *reinterpret_cast<float2*>(C + (size_t)(row0 + 8) * Nn + col0) = make_float2(v10, v11);
        }
    }
}

// ===========================================================================
// Flash attention via tf32 mma.sync. One block = (b, h), BQ=128, BC=64.
// Inputs (qkv) are PRE-ROUNDED tf32 -> no cvt in staging. Output rounded.
// ===========================================================================
#define APAD 68
#define ASM_K  0
#define ASM_VT (64 * APAD)
#define ASM_P  (2 * 64 * APAD)
#define ATTN_SMEM ((2 * 64 * APAD + 128 * APAD) * 4)   // 69632 B

__global__ __launch_bounds__(256)
void attn_mma(const float* __restrict__ qkv, float* __restrict__ att) {
    extern __shared__ float sm[];
    float* sK  = sm + ASM_K;
    float* sVt = sm + ASM_VT;
    float* sP  = sm + ASM_P;

    int tid = threadIdx.x, lane = tid & 31, wid = tid >> 5;
    int r = lane >> 2, cq = lane & 3;
    int qt = blockIdx.x, h = blockIdx.y, b = blockIdx.z;
    int q0 = qt * 128;

    const float* qbase = qkv + (size_t)b * SEQ * QKVW + h * DH;
    const float* kbase = qbase + INNER;
    const float* vbase = qbase + 2 * INNER;

    // ---- Stage Q (x0.125 exact scale; values already tf32) through sP
    #pragma unroll
    for (int i = 0; i < 8; i++) {
        int idx = i * 256 + tid;
        int row = idx >> 4, d4 = (idx & 15) << 2;
        float4 v = *reinterpret_cast<const float4*>(qbase + (size_t)(q0 + row) * QKVW + d4);
        float* p = &sP[row * APAD + d4];
        p[0] = v.x * 0.125f; p[1] = v.y * 0.125f;
        p[2] = v.z * 0.125f; p[3] = v.w * 0.125f;
    }
    __syncthreads();
    uint32_t qf[8][4];
    #pragma unroll
    for (int kt = 0; kt < 8; kt++) {
        const float* p = &sP[(wid * 16 + r) * APAD + kt * 8 + cq];
        qf[kt][0] = __float_as_uint(p[0]);
        qf[kt][1] = __float_as_uint(p[8 * APAD]);
        qf[kt][2] = __float_as_uint(p[4]);
        qf[kt][3] = __float_as_uint(p[8 * APAD + 4]);
    }

    float m0 = -1e30f, m1 = -1e30f, l0 = 0.f, l1 = 0.f;
    float o[8][4];
    #pragma unroll
    for (int nt = 0; nt < 8; nt++)
        #pragma unroll
        for (int j = 0; j < 4; j++) o[nt][j] = 0.f;

    int nchunk = 2 * qt + 2;
    for (int c = 0; c < nchunk; c++) {
        __syncthreads();
        #pragma unroll
        for (int i = 0; i < 4; i++) {
            int idx = i * 256 + tid;
            int row = idx >> 4, d4 = (idx & 15) << 2;
            float4 kv = *reinterpret_cast<const float4*>(kbase + (size_t)(c * 64 + row) * QKVW + d4);
            *reinterpret_cast<float4*>(&sK[row * APAD + d4]) = kv;
            float4 vv = *reinterpret_cast<const float4*>(vbase + (size_t)(c * 64 + row) * QKVW + d4);
            sVt[(d4 + 0) * APAD + row] = vv.x;
            sVt[(d4 + 1) * APAD + row] = vv.y;
            sVt[(d4 + 2) * APAD + row] = vv.z;
            sVt[(d4 + 3) * APAD + row] = vv.w;
        }
        __syncthreads();

        int wrow0 = q0 + wid * 16;
        if (wrow0 + 15 < c * 64) continue;

        float s[8][4];
        #pragma unroll
        for (int nt = 0; nt < 8; nt++)
            #pragma unroll
            for (int j = 0; j < 4; j++) s[nt][j] = 0.f;
        #pragma unroll
        for (int kt = 0; kt < 8; kt++) {
            uint32_t bf[8][2];
            #pragma unroll
            for (int nt = 0; nt < 8; nt++) {
                const float* kp = &sK[(nt * 8 + r) * APAD + kt * 8 + cq];
                bf[nt][0] = __float_as_uint(kp[0]);
                bf[nt][1] = __float_as_uint(kp[4]);
            }
            #pragma unroll
            for (int nt = 0; nt < 8; nt++)
                mma_tf32_16x8x8(s[nt], qf[kt], bf[nt]);
        }

        if (c * 64 + 63 > wrow0) {
            int row_a = wrow0 + r, row_b = wrow0 + r + 8;
            #pragma unroll
            for (int nt = 0; nt < 8; nt++) {
                int col = c * 64 + nt * 8 + 2 * cq;
                if (col     > row_a) s[nt][0] = -1e30f;
                if (col + 1 > row_a) s[nt][1] = -1e30f;
                if (col     > row_b) s[nt][2] = -1e30f;
                if (col + 1 > row_b) s[nt][3] = -1e30f;
            }
        }

        float mt0 = -1e30f, mt1 = -1e30f;
        #pragma unroll
        for (int nt = 0; nt < 8; nt++) {
            mt0 = fmaxf(mt0, fmaxf(s[nt][0], s[nt][1]));
            mt1 = fmaxf(mt1, fmaxf(s[nt][2], s[nt][3]));
        }
        mt0 = fmaxf(mt0, __shfl_xor_sync(0xFFFFFFFFu, mt0, 1));
        mt0 = fmaxf(mt0, __shfl_xor_sync(0xFFFFFFFFu, mt0, 2));
        mt1 = fmaxf(mt1, __shfl_xor_sync(0xFFFFFFFFu, mt1, 1));
        mt1 = fmaxf(mt1, __shfl_xor_sync(0xFFFFFFFFu, mt1, 2));

        float mn0 = fmaxf(m0, mt0), mn1 = fmaxf(m1, mt1);
        float a0 = __expf(m0 - mn0), a1 = __expf(m1 - mn1);
        m0 = mn0; m1 = mn1;
        float rs0 = 0.f, rs1 = 0.f;
        #pragma unroll
        for (int nt = 0; nt < 8; nt++) {
            s[nt][0] = __expf(s[nt][0] - mn0);
            s[nt][1] = __expf(s[nt][1] - mn0);
            s[nt][2] = __expf(s[nt][2] - mn1);
            s[nt][3] = __expf(s[nt][3] - mn1);
            rs0 += s[nt][0] + s[nt][1];
            rs1 += s[nt][2] + s[nt][3];
        }
        rs0 += __shfl_xor_sync(0xFFFFFFFFu, rs0, 1);
        rs0 += __shfl_xor_sync(0xFFFFFFFFu, rs0, 2);
        rs1 += __shfl_xor_sync(0xFFFFFFFFu, rs1, 1);
        rs1 += __shfl_xor_sync(0xFFFFFFFFu, rs1, 2);
        l0 = l0 * a0 + rs0;
        l1 = l1 * a1 + rs1;
        #pragma unroll
        for (int nt = 0; nt < 8; nt++) {
            o[nt][0] *= a0; o[nt][1] *= a0;
            o[nt][2] *= a1; o[nt][3] *= a1;
        }

        float* pr0 = &sP[(wid * 16 + r) * APAD];
        float* pr1 = &sP[(wid * 16 + r + 8) * APAD];
        #pragma unroll
        for (int nt = 0; nt < 8; nt++) {
            int col = nt * 8 + 2 * cq;
            pr0[col]     = cvt_tf32_f(s[nt][0]);
            pr0[col + 1] = cvt_tf32_f(s[nt][1]);
            pr1[col]     = cvt_tf32_f(s[nt][2]);
            pr1[col + 1] = cvt_tf32_f(s[nt][3]);
        }
        __syncwarp();

        #pragma unroll
        for (int kt = 0; kt < 8; kt++) {
            uint32_t pf[4];
            const float* pp = &sP[(wid * 16 + r) * APAD + kt * 8 + cq];
            pf[0] = __float_as_uint(pp[0]);
            pf[1] = __float_as_uint(pp[8 * APAD]);
            pf[2] = __float_as_uint(pp[4]);
            pf[3] = __float_as_uint(pp[8 * APAD + 4]);
            uint32_t bf[8][2];
            #pragma unroll
            for (int nt = 0; nt < 8; nt++) {
                const float* vp = &sVt[(nt * 8 + r) * APAD + kt * 8 + cq];
                bf[nt][0] = __float_as_uint(vp[0]);
                bf[nt][1] = __float_as_uint(vp[4]);
            }
            #pragma unroll
            for (int nt = 0; nt < 8; nt++)
                mma_tf32_16x8x8(o[nt], pf, bf[nt]);
        }
        __syncwarp();
    }

    float inv0 = 1.f / l0, inv1 = 1.f / l1;
    int row_a = q0 + wid * 16 + r, row_b = row_a + 8;
    #pragma unroll
    for (int nt = 0; nt < 8; nt++) {
        int col = h * DH + nt * 8 + 2 * cq;
        *reinterpret_cast<float2*>(att + ((size_t)b * SEQ + row_a) * INNER + col) =
            make_float2(cvt_tf32_f(o[nt][0] * inv0), cvt_tf32_f(o[nt][1] * inv0));
        *reinterpret_cast<float2*>(att + ((size_t)b * SEQ + row_b) * INNER + col) =
            make_float2(cvt_tf32_f(o[nt][2] * inv1), cvt_tf32_f(o[nt][3] * inv1));
    }
}

// ===========================================================================
extern "C" void kernel_launch(void* const* d_in, const int* in_sizes, int n_in,
                              void* d_out, int out_size) {
    const float* x     = (const float*)d_in[0];
    const float* gamma = (const float*)d_in[1];
    const float* beta  = (const float*)d_in[2];
    const float* w_qkv = (const float*)d_in[3];
    const float* w_out = (const float*)d_in[4];
    float* out = (float*)d_out;

    float *xn, *qkv, *att, *wqkvT, *woutT;
    cudaGetSymbolAddress((void**)&xn,    g_xn);
    cudaGetSymbolAddress((void**)&qkv,   g_qkv);
    cudaGetSymbolAddress((void**)&att,   g_att);
    cudaGetSymbolAddress((void**)&wqkvT, g_wqkvT);
    cudaGetSymbolAddress((void**)&woutT, g_woutT);

    cudaFuncSetAttribute(gemm_tf32<true>,  cudaFuncAttributeMaxDynamicSharedMemorySize, GEMM_SMEM);
    cudaFuncSetAttribute(gemm_tf32<false>, cudaFuncAttributeMaxDynamicSharedMemorySize, GEMM_SMEM);
    cudaFuncSetAttribute(attn_mma, cudaFuncAttributeMaxDynamicSharedMemorySize, ATTN_SMEM);

    ln_kernel<<<ROWS, 256>>>(x, gamma, beta, xn);
    transpose_cvt<<<dim3(QKVW / 32, DIMD / 32), dim3(32, 8)>>>(w_qkv, wqkvT, DIMD, QKVW);
    transpose_cvt<<<dim3(DIMD / 32, INNER / 32), dim3(32, 8)>>>(w_out, woutT, INNER, DIMD);
    gemm_tf32<true><<<dim3(QKVW / 128, ROWS / 128), 256, GEMM_SMEM>>>(xn, wqkvT, qkv, ROWS, QKVW, DIMD);
    attn_mma<<<dim3(SEQ / 128, HEADS, BATCH), 256, ATTN_SMEM>>>(qkv, att);
    gemm_tf32<false><<<dim3(DIMD / 128, ROWS / 128), 256, GEMM_SMEM>>>(att, woutT, out, ROWS, DIMD, INNER);
}